// round 9
// baseline (speedup 1.0000x reference)
#include <cuda_runtime.h>
#include <cuda_bf16.h>
#include <cuda_fp16.h>
#include <cooperative_groups.h>
#include <math.h>

namespace cg = cooperative_groups;

#define NN 50000
#define EE 400000
#define HID 64
#define HEADS 4
#define INDIM 128

typedef unsigned long long u64;

// ---------------- scratch (no allocations allowed) ----------------
__device__ int   g_deg[NN];           // zero at load; reset in phase E each run
__device__ int   g_row_ptr[NN + 1];
__device__ int   g_cursor[NN];
__device__ int   g_csr[EE + NN];
__device__ int   g_pdst[EE + NN];
__device__ float g_dinv[NN];
__device__ __align__(16) float   g_ws[HEADS * HID];
__device__ __align__(16) float   g_wd[HEADS * HID];
__device__ __align__(16) float   g_xw[NN * HID];
__device__ __align__(16) float   g_h1[NN * HID];
__device__ __align__(16) __half2 g_h1h[NN * 32];     // fp16 h1 for GAT gather only
__device__ __align__(16) float   g_as[NN * HEADS];
__device__ __align__(16) float   g_ad[NN * HEADS];
__device__ __align__(16) float4  g_exf[EE + NN];     // per-edge exp weights, fp32
__device__ __align__(16) float   g_u[NN * HEADS * HID];
__device__ __align__(16) float   g_hp[NN * HID];

// ---------------- packed f32x2 helpers (SASS FFMA2 path) ----------------
__device__ __forceinline__ u64 pack2(float lo, float hi) {
    u64 r; asm("mov.b64 %0, {%1, %2};" : "=l"(r) : "f"(lo), "f"(hi)); return r;
}
__device__ __forceinline__ void ffma2(u64& d, u64 a, u64 b) {
    asm("fma.rn.f32x2 %0, %1, %2, %0;" : "+l"(d) : "l"(a), "l"(b));
}
__device__ __forceinline__ float2 unpack2(u64 v) {
    float2 f; asm("mov.b64 {%0, %1}, %2;" : "=f"(f.x), "=f"(f.y) : "l"(v)); return f;
}
__device__ __forceinline__ float lrelu(float v) { return fmaxf(v, 0.2f * v); }

// =================== ONE cooperative persistent kernel ===================
__global__ void __launch_bounds__(256, 3) mega_kernel(
    const float* __restrict__ x, const void* __restrict__ ei,
    const float* __restrict__ W_gcn, const float* __restrict__ b_gcn,
    const float* __restrict__ Wg, const float* __restrict__ b_gat,
    const float* __restrict__ att_src, const float* __restrict__ att_dst,
    const float* __restrict__ Wp, const float* __restrict__ b_patch,
    const float* __restrict__ gamma, const float* __restrict__ beta,
    float* __restrict__ out, int n, int E)
{
    cg::grid_group grid = cg::this_grid();
    __shared__ float smem[12288];            // 48 KB, reused per phase
    int tid = threadIdx.x, lane = tid & 31, wid = tid >> 5;
    int cta = blockIdx.x, nCTA = gridDim.x;
    int* ismem = (int*)smem;

    // ---- detect dtype (per-CTA, no sync needed across grid) ----
    int is64;
    {
        int c = 0;
        const int* w = (const int*)ei;
        for (int k = tid; k < 2048; k += 256) if (w[2 * k + 1] != 0) c++;
#pragma unroll
        for (int off = 16; off; off >>= 1) c += __shfl_xor_sync(0xffffffffu, c, off);
        if (tid == 0) ismem[0] = 0;
        __syncthreads();
        if (lane == 0) atomicAdd(&ismem[0], c);
        __syncthreads();
        is64 = (ismem[0] < 100) ? 1 : 0;
        __syncthreads();
    }

    // ================= PHASE A: prep (CTA0) + hist + gemm1 =================
    if (cta == 0) {                          // rank-1 attention weights
        int h = tid >> 6, k = tid & 63;
        float ss = 0.f, sd = 0.f;
        for (int ch = 0; ch < HID; ch++) {
            float w = Wg[k * 256 + h * 64 + ch];
            ss += w * att_src[h * 64 + ch];
            sd += w * att_dst[h * 64 + ch];
        }
        g_ws[tid] = ss;
        g_wd[tid] = sd;
    }
    if (is64) {
        const long long* e64 = (const long long*)ei;
        for (int i = cta * 256 + tid; i < E; i += nCTA * 256)
            atomicAdd(&g_deg[(int)e64[E + i]], 1);
    } else {
        const int* e32 = (const int*)ei;
        for (int i = cta * 256 + tid; i < E; i += nCTA * 256)
            atomicAdd(&g_deg[e32[E + i]], 1);
    }
    {   // gemm1 tiles: xw = x @ W_gcn  [N,128]@[128,64]
        float* Ws = smem;                    // 8192 floats
        float* xs = smem + 8192;             // 4096 floats
        for (int i = tid; i < INDIM * HID; i += 256) Ws[i] = W_gcn[i];
        const float4* x4 = (const float4*)x;
        float4* xs4 = (float4*)xs;
        const float4* Ws4 = (const float4*)Ws;
        int q = tid & 15, rg = tid >> 4;
        int ntiles = (n + 127) >> 7;
        for (int tile = cta; tile < ntiles; tile += nCTA) {
            int rowbase = tile << 7;
            u64 aXY[8], aZW[8];
#pragma unroll
            for (int j = 0; j < 8; j++) { aXY[j] = 0ull; aZW[j] = 0ull; }
            for (int ch = 0; ch < 4; ch++) {
                __syncthreads();
                for (int l = tid; l < 1024; l += 256) {
                    int r = l >> 3, c4 = l & 7;
                    int row = rowbase + r;
                    float4 v = make_float4(0.f, 0.f, 0.f, 0.f);
                    if (row < n) v = x4[row * 32 + ch * 8 + c4];
                    xs4[r * 8 + c4] = v;
                }
                __syncthreads();
#pragma unroll 4
                for (int kk = 0; kk < 32; kk++) {
                    float4 w = Ws4[(ch * 32 + kk) * 16 + q];
                    u64 wxy = pack2(w.x, w.y), wzw = pack2(w.z, w.w);
#pragma unroll
                    for (int j = 0; j < 8; j++) {
                        float xv = xs[(rg * 8 + j) * 32 + kk];
                        u64 xv2 = pack2(xv, xv);
                        ffma2(aXY[j], xv2, wxy);
                        ffma2(aZW[j], xv2, wzw);
                    }
                }
            }
            float4* xw4 = (float4*)g_xw;
#pragma unroll
            for (int j = 0; j < 8; j++) {
                int row = rowbase + rg * 8 + j;
                if (row < n) {
                    float2 lo = unpack2(aXY[j]), hi = unpack2(aZW[j]);
                    xw4[row * 16 + q] = make_float4(lo.x, lo.y, hi.x, hi.y);
                }
            }
        }
    }
    grid.sync();

    // ================= PHASE B: scan (CTAs < nb) =================
    {
        int nb = (n + 255) >> 8;
        if (cta < nb) {
            int b = cta;
            int lim = b * 256;
            int part = 0;
            for (int i = tid; i < lim; i += 256) part += g_deg[i];
#pragma unroll
            for (int off = 16; off; off >>= 1) part += __shfl_xor_sync(0xffffffffu, part, off);
            __syncthreads();
            if (lane == 0) ismem[wid] = part;
            __syncthreads();
            if (tid == 0) {
                int a = 0;
#pragma unroll
                for (int w = 0; w < 8; w++) a += ismem[w];
                ismem[8] = a + lim;
            }
            __syncthreads();
            int off0 = ismem[8];
            int i = b * 256 + tid;
            int v = (i < n) ? (g_deg[i] + 1) : 0;
            int xsc = v;
#pragma unroll
            for (int off = 1; off < 32; off <<= 1) {
                int y = __shfl_up_sync(0xffffffffu, xsc, off);
                if (lane >= off) xsc += y;
            }
            __syncthreads();
            if (lane == 31) ismem[wid] = xsc;
            __syncthreads();
            int excl_w = 0;
            for (int w = 0; w < 8; w++) if (w < wid) excl_w += ismem[w];
            if (i < n) {
                int rp = off0 + excl_w + xsc - v;
                g_row_ptr[i] = rp;
                g_cursor[i] = rp;
                g_dinv[i] = rsqrtf((float)v);
            }
            if (b == 0 && tid == 0) g_row_ptr[n] = E + n;
            __syncthreads();
        }
    }
    grid.sync();

    // ================= PHASE C: CSR fill =================
    {
        int total = E + n;
        for (int i = cta * 256 + tid; i < total; i += nCTA * 256) {
            int s, d;
            if (i < E) {
                if (is64) {
                    s = (int)((const long long*)ei)[i];
                    d = (int)((const long long*)ei)[E + i];
                } else {
                    s = ((const int*)ei)[i];
                    d = ((const int*)ei)[E + i];
                }
            } else { s = d = i - E; }
            int pos = atomicAdd(&g_cursor[d], 1);
            g_csr[pos] = s;
            g_pdst[pos] = d;
        }
    }
    grid.sync();

    // ================= PHASE D: GCN aggregate + attention dots =================
    {
        const float2* xw2 = (const float2*)g_xw;
        const float2* ws2 = (const float2*)g_ws;
        const float2* wd2 = (const float2*)g_wd;
        int stride = nCTA * 8;
        for (int node = cta * 8 + wid; node < n; node += stride) {
            int start = g_row_ptr[node], end = g_row_ptr[node + 1];
            float dn = g_dinv[node];
            float2 acc = make_float2(0.f, 0.f);
            int s_next = (start < end) ? g_csr[start] : 0;
            for (int e = start; e < end; e++) {
                int s = s_next;
                if (e + 1 < end) s_next = g_csr[e + 1];
                float w = g_dinv[s] * dn;
                float2 v = xw2[s * 32 + lane];
                acc.x += w * v.x; acc.y += w * v.y;
            }
            float2 b = ((const float2*)b_gcn)[lane];
            float2 o;
            o.x = fmaxf(acc.x + b.x, 0.f);
            o.y = fmaxf(acc.y + b.y, 0.f);
            ((float2*)g_h1)[node * 32 + lane] = o;
            g_h1h[node * 32 + lane] = __floats2half2_rn(o.x, o.y);

            float p[8];
#pragma unroll
            for (int h = 0; h < 4; h++) {
                float2 ws = ws2[h * 32 + lane];
                float2 wd = wd2[h * 32 + lane];
                p[h]     = o.x * ws.x + o.y * ws.y;
                p[4 + h] = o.x * wd.x + o.y * wd.y;
            }
#pragma unroll
            for (int off = 16; off; off >>= 1) {
#pragma unroll
                for (int j = 0; j < 8; j++) p[j] += __shfl_xor_sync(0xffffffffu, p[j], off);
            }
            if (lane == 0) {
                ((float4*)g_as)[node] = make_float4(p[0], p[1], p[2], p[3]);
                ((float4*)g_ad)[node] = make_float4(p[4], p[5], p[6], p[7]);
            }
        }
    }
    grid.sync();

    // ================= PHASE E: edge exp (no max-sub; fp32 safe) + deg reset =================
    {
        int total = E + n;
        for (int p = cta * 256 + tid; p < total; p += nCTA * 256) {
            int s = g_csr[p];
            int d = g_pdst[p];
            float4 a  = ((const float4*)g_as)[s];
            float4 ad = ((const float4*)g_ad)[d];
            float4 o;
            o.x = __expf(lrelu(a.x + ad.x));
            o.y = __expf(lrelu(a.y + ad.y));
            o.z = __expf(lrelu(a.z + ad.z));
            o.w = __expf(lrelu(a.w + ad.w));
            g_exf[p] = o;
        }
        for (int i = cta * 256 + tid; i < n; i += nCTA * 256) g_deg[i] = 0;
    }
    grid.sync();

    // ================= PHASE F: GAT aggregate, then patch GEMM =================
    {
        int stride = nCTA * 8;
        for (int node = cta * 8 + wid; node < n; node += stride) {
            int start = g_row_ptr[node], end = g_row_ptr[node + 1];
            float acc[8];
#pragma unroll
            for (int i = 0; i < 8; i++) acc[i] = 0.f;
            float d0 = 0.f, d1 = 0.f, d2 = 0.f, d3 = 0.f;
            int s_cur = (start < end) ? g_csr[start] : 0;
            float4 ex_cur = (start < end) ? g_exf[start] : make_float4(0.f, 0.f, 0.f, 0.f);
            for (int e = start; e < end; e++) {
                int s = s_cur;
                float4 ex = ex_cur;
                if (e + 1 < end) { s_cur = g_csr[e + 1]; ex_cur = g_exf[e + 1]; }
                d0 += ex.x; d1 += ex.y; d2 += ex.z; d3 += ex.w;
                float2 hv = __half22float2(g_h1h[s * 32 + lane]);
                acc[0] += ex.x * hv.x; acc[1] += ex.x * hv.y;
                acc[2] += ex.y * hv.x; acc[3] += ex.y * hv.y;
                acc[4] += ex.z * hv.x; acc[5] += ex.z * hv.y;
                acc[6] += ex.w * hv.x; acc[7] += ex.w * hv.y;
            }
            float r0 = 1.f / d0, r1 = 1.f / d1, r2 = 1.f / d2, r3 = 1.f / d3;
            float2* u2 = (float2*)g_u;
            u2[node * 128 +       lane] = make_float2(acc[0] * r0, acc[1] * r0);
            u2[node * 128 +  32 + lane] = make_float2(acc[2] * r1, acc[3] * r1);
            u2[node * 128 +  64 + lane] = make_float2(acc[4] * r2, acc[5] * r2);
            u2[node * 128 +  96 + lane] = make_float2(acc[6] * r3, acc[7] * r3);
        }
        __syncthreads();
        // ---- patch tiles: hp = h1 @ Wp + bp ----
        float* Ws = smem;                    // 4096 floats
        float* hs = smem + 4096;             // 8192 floats
        for (int i = tid; i < HID * HID; i += 256) Ws[i] = Wp[i];
        const float4* h1_4 = (const float4*)g_h1;
        float4* hs4 = (float4*)hs;
        const float4* Ws4 = (const float4*)Ws;
        int q = tid & 15, rg = tid >> 4;
        int ntiles = (n + 127) >> 7;
        for (int tile = cta; tile < ntiles; tile += nCTA) {
            int rowbase = tile << 7;
            __syncthreads();
            for (int l = tid; l < 2048; l += 256) {
                int r = l >> 4, c4 = l & 15;
                int row = rowbase + r;
                hs4[l] = (row < n) ? h1_4[row * 16 + c4] : make_float4(0.f, 0.f, 0.f, 0.f);
            }
            __syncthreads();
            u64 aXY[8], aZW[8];
#pragma unroll
            for (int j = 0; j < 8; j++) { aXY[j] = 0ull; aZW[j] = 0ull; }
#pragma unroll 4
            for (int k = 0; k < HID; k++) {
                float4 w = Ws4[k * 16 + q];
                u64 wxy = pack2(w.x, w.y), wzw = pack2(w.z, w.w);
#pragma unroll
                for (int j = 0; j < 8; j++) {
                    float hv = hs[(rg * 8 + j) * HID + k];
                    u64 hv2 = pack2(hv, hv);
                    ffma2(aXY[j], hv2, wxy);
                    ffma2(aZW[j], hv2, wzw);
                }
            }
            float4 bp = ((const float4*)b_patch)[q];
            float4* hp4 = (float4*)g_hp;
#pragma unroll
            for (int j = 0; j < 8; j++) {
                int row = rowbase + rg * 8 + j;
                if (row < n) {
                    float2 lo = unpack2(aXY[j]), hi = unpack2(aZW[j]);
                    hp4[row * 16 + q] = make_float4(lo.x + bp.x, lo.y + bp.y,
                                                    hi.x + bp.z, hi.y + bp.w);
                }
            }
        }
    }
    grid.sync();

    // ================= PHASE G: gemm2b + residual + LayerNorm =================
    {
        float* Wc = smem;                    // 4096 floats
        float* us = smem + 4096;             // 8192 floats
        const float4* Wg4 = (const float4*)Wg;
        const float4* u4 = (const float4*)g_u;
        float4* Wc4s = (float4*)Wc;
        float4* us4 = (float4*)us;
        const float4* Wc4 = (const float4*)Wc;
        int q = tid & 15, rg = tid >> 4;
        int ntiles = (n + 127) >> 7;
        for (int tile = cta; tile < ntiles; tile += nCTA) {
            int rowbase = tile << 7;
            u64 aXY[8], aZW[8];
#pragma unroll
            for (int j = 0; j < 8; j++) { aXY[j] = 0ull; aZW[j] = 0ull; }
            for (int h = 0; h < 4; h++) {
                __syncthreads();
                for (int i = tid; i < 1024; i += 256) {
                    int k = i >> 4, j = i & 15;
                    Wc4s[i] = Wg4[k * 64 + h * 16 + j];
                }
                for (int i = tid; i < 2048; i += 256) {
                    int r = i >> 4, j = i & 15;
                    int row = rowbase + r;
                    us4[i] = (row < n) ? u4[row * 64 + h * 16 + j] : make_float4(0.f, 0.f, 0.f, 0.f);
                }
                __syncthreads();
#pragma unroll 4
                for (int k = 0; k < HID; k++) {
                    float4 w = Wc4[k * 16 + q];
                    u64 wxy = pack2(w.x, w.y), wzw = pack2(w.z, w.w);
#pragma unroll
                    for (int j = 0; j < 8; j++) {
                        float hv = us[(rg * 8 + j) * HID + k];
                        u64 hv2 = pack2(hv, hv);
                        ffma2(aXY[j], hv2, wxy);
                        ffma2(aZW[j], hv2, wzw);
                    }
                }
            }
            float4 b   = ((const float4*)b_gat)[q];
            float4 g4  = ((const float4*)gamma)[q];
            float4 bt4 = ((const float4*)beta)[q];
            const float4* h1_4 = (const float4*)g_h1;
            const float4* hp4  = (const float4*)g_hp;
            float4* out4 = (float4*)out;
#pragma unroll
            for (int j = 0; j < 8; j++) {
                int row = rowbase + rg * 8 + j;
                float2 lo = unpack2(aXY[j]), hi = unpack2(aZW[j]);
                float4 h2v;
                h2v.x = fmaxf(0.25f * lo.x + b.x, 0.f);
                h2v.y = fmaxf(0.25f * lo.y + b.y, 0.f);
                h2v.z = fmaxf(0.25f * hi.x + b.z, 0.f);
                h2v.w = fmaxf(0.25f * hi.y + b.w, 0.f);
                float4 h1v = (row < n) ? h1_4[row * 16 + q] : make_float4(0.f, 0.f, 0.f, 0.f);
                float4 hpv = (row < n) ? hp4[row * 16 + q]  : make_float4(0.f, 0.f, 0.f, 0.f);
                float4 h;
                h.x = h1v.x + h2v.x + hpv.x;
                h.y = h1v.y + h2v.y + hpv.y;
                h.z = h1v.z + h2v.z + hpv.z;
                h.w = h1v.w + h2v.w + hpv.w;
                float s  = h.x + h.y + h.z + h.w;
                float sq = h.x * h.x + h.y * h.y + h.z * h.z + h.w * h.w;
#pragma unroll
                for (int off = 8; off; off >>= 1) {
                    s  += __shfl_xor_sync(0xffffffffu, s, off);
                    sq += __shfl_xor_sync(0xffffffffu, sq, off);
                }
                float mu = s * (1.f / 64.f);
                float var = sq * (1.f / 64.f) - mu * mu;
                float rstd = rsqrtf(var + 1e-5f);
                if (row < n) {
                    float4 o;
                    o.x = (h.x - mu) * rstd * g4.x + bt4.x;
                    o.y = (h.y - mu) * rstd * g4.y + bt4.y;
                    o.z = (h.z - mu) * rstd * g4.z + bt4.z;
                    o.w = (h.w - mu) * rstd * g4.w + bt4.w;
                    out4[row * 16 + q] = o;
                }
            }
        }
    }
}

// ---------------- launch: single cooperative kernel ----------------
extern "C" void kernel_launch(void* const* d_in, const int* in_sizes, int n_in,
                              void* d_out, int out_size) {
    const float* x        = (const float*)d_in[0];
    const void*  ei       = d_in[1];
    const float* W_gcn    = (const float*)d_in[2];
    const float* b_gcn    = (const float*)d_in[3];
    const float* W_gat    = (const float*)d_in[4];
    const float* att_src  = (const float*)d_in[5];
    const float* att_dst  = (const float*)d_in[6];
    const float* b_gat    = (const float*)d_in[7];
    const float* W_patch  = (const float*)d_in[8];
    const float* b_patch  = (const float*)d_in[9];
    const float* gamma    = (const float*)d_in[10];
    const float* beta     = (const float*)d_in[11];
    float* out = (float*)d_out;

    int n = in_sizes[0] / INDIM;          // 50000
    int E = in_sizes[1] / 2;              // 400000

    // one-time occupancy query (pre-capture correctness run sets it)
    static int nBlocks = 0;
    if (nBlocks == 0) {
        int dev = 0;
        cudaGetDevice(&dev);
        int smCount = 0;
        cudaDeviceGetAttribute(&smCount, cudaDevAttrMultiProcessorCount, dev);
        int perSM = 0;
        cudaOccupancyMaxActiveBlocksPerMultiprocessor(&perSM, mega_kernel, 256, 0);
        if (perSM < 1) perSM = 1;
        nBlocks = smCount * perSM;
    }

    void* args[] = {
        (void*)&x, (void*)&ei, (void*)&W_gcn, (void*)&b_gcn,
        (void*)&W_gat, (void*)&b_gat, (void*)&att_src, (void*)&att_dst,
        (void*)&W_patch, (void*)&b_patch, (void*)&gamma, (void*)&beta,
        (void*)&out, (void*)&n, (void*)&E
    };
    cudaLaunchCooperativeKernel((void*)mega_kernel, dim3(nBlocks), dim3(256),
                                args, 0, (cudaStream_t)0);
}

// round 10
// speedup vs baseline: 1.9603x; 1.9603x over previous
#include <cuda_runtime.h>
#include <cuda_bf16.h>
#include <cuda_fp16.h>
#include <mma.h>
#include <math.h>

using namespace nvcuda;

#define NN 50000
#define NPAD 50048
#define EE 400000
#define HID 64
#define HEADS 4
#define INDIM 128

typedef unsigned long long u64;

// ---------------- scratch (no allocations allowed) ----------------
__device__ int   g_deg[NN];           // zero at load; gcn_agg resets each run
__device__ int   g_row_ptr[NN + 1];
__device__ int   g_cursor[NN];
__device__ int   g_csr[EE + NN];
__device__ int   g_pdst[EE + NN];
__device__ float g_dinv[NN];
__device__ __align__(16) float   g_ws[HEADS * HID];
__device__ __align__(16) float   g_wd[HEADS * HID];
__device__ __align__(16) __half  g_wsth[256 * HID];  // Wstack fp16 [256,64] row-major
__device__ __align__(16) float   g_xw[NN * HID];
__device__ __align__(16) float   g_h1[NN * HID];
__device__ __align__(16) __half2 g_h1h[NN * 32];     // fp16 h1 for GAT gather
__device__ __align__(16) float   g_as[NN * HEADS];
__device__ __align__(16) float   g_ad[NN * HEADS];
__device__ __align__(16) float4  g_exf[EE + NN];     // per-edge exp weights, fp32
__device__ __align__(16) __half  g_uh[NPAD * 256];   // alpha-aggregated h1, fp16 [N,256]
__device__ __align__(16) float   g_hp[NN * HID];

// ---------------- packed f32x2 helpers (SASS FFMA2 path) ----------------
__device__ __forceinline__ u64 pack2(float lo, float hi) {
    u64 r; asm("mov.b64 %0, {%1, %2};" : "=l"(r) : "f"(lo), "f"(hi)); return r;
}
__device__ __forceinline__ void ffma2(u64& d, u64 a, u64 b) {
    asm("fma.rn.f32x2 %0, %1, %2, %0;" : "+l"(d) : "l"(a), "l"(b));
}
__device__ __forceinline__ float2 unpack2(u64 v) {
    float2 f; asm("mov.b64 {%0, %1}, %2;" : "=f"(f.x), "=f"(f.y) : "l"(v)); return f;
}
__device__ __forceinline__ float lrelu(float v) { return fmaxf(v, 0.2f * v); }

// per-CTA dtype detect (deterministic; reads 8KB of edge words, L2-hot)
__device__ __forceinline__ int detect_is64(const void* ei, int* ismem) {
    int t = threadIdx.x;
    int c = 0;
    const int* w = (const int*)ei;
    for (int k = t; k < 2048; k += blockDim.x) if (w[2 * k + 1] != 0) c++;
#pragma unroll
    for (int off = 16; off; off >>= 1) c += __shfl_xor_sync(0xffffffffu, c, off);
    if (t == 0) ismem[0] = 0;
    __syncthreads();
    if ((t & 31) == 0) atomicAdd(&ismem[0], c);
    __syncthreads();
    int r = (ismem[0] < 100) ? 1 : 0;
    __syncthreads();
    return r;
}

// ---------------- rank-1 attention weights + fp16 Wstack (side stream) ----------------
__global__ void prep2_kernel(const float* __restrict__ Wg,
                             const float* __restrict__ att_src,
                             const float* __restrict__ att_dst) {
    int t = threadIdx.x;            // t = h*64 + k
    int h = t >> 6, k = t & 63;
    float ss = 0.f, sd = 0.f;
    for (int ch = 0; ch < HID; ch++) {
        float w = Wg[k * 256 + h * 64 + ch];
        ss += w * att_src[h * 64 + ch];
        sd += w * att_dst[h * 64 + ch];
    }
    g_ws[t] = ss;
    g_wd[t] = sd;
    // Wstack fp16: wsth[(h*64+kk)*64 + c] = Wg[kk*256 + h*64 + c]
    for (int i = t; i < 256 * HID; i += 256) {
        int hh = i >> 12, kk = (i >> 6) & 63, c = i & 63;
        g_wsth[i] = __float2half(Wg[kk * 256 + hh * 64 + c]);
    }
}

// ---------------- degree histogram (per-CTA detect, 4 edges/thread) ----------------
__global__ void hist_kernel(const void* ei, int E) {
    __shared__ int ismem[1];
    int is64 = detect_is64(ei, ismem);
    int i = blockIdx.x * blockDim.x + threadIdx.x;
    int base = i * 4;
    if (base >= E) return;
    if (is64) {
        const long long* e64 = (const long long*)ei;
        int lim = min(base + 4, E);
        for (int k = base; k < lim; k++)
            atomicAdd(&g_deg[(int)e64[E + k]], 1);
    } else {
        if (base + 4 <= E) {
            int4 v = *(const int4*)((const int*)ei + E + base);
            atomicAdd(&g_deg[v.x], 1);
            atomicAdd(&g_deg[v.y], 1);
            atomicAdd(&g_deg[v.z], 1);
            atomicAdd(&g_deg[v.w], 1);
        } else {
            for (int k = base; k < E; k++)
                atomicAdd(&g_deg[((const int*)ei)[E + k]], 1);
        }
    }
}

// ---------------- single-kernel scan: block sums its prefix directly ----------------
__global__ void scan_kernel(int n, int total) {
    __shared__ int wsum[8];
    __shared__ int s_off;
    int t = threadIdx.x, lane = t & 31, wid = t >> 5, b = blockIdx.x;
    int lim = b * 256;
    int part = 0;
    for (int i = t; i < lim; i += 256) part += g_deg[i];
#pragma unroll
    for (int off = 16; off; off >>= 1) part += __shfl_xor_sync(0xffffffffu, part, off);
    if (lane == 0) wsum[wid] = part;
    __syncthreads();
    if (t == 0) {
        int a = 0;
#pragma unroll
        for (int w = 0; w < 8; w++) a += wsum[w];
        s_off = a + lim;
    }
    __syncthreads();
    int off0 = s_off;
    int i = b * 256 + t;
    int v = (i < n) ? (g_deg[i] + 1) : 0;
    int x = v;
#pragma unroll
    for (int off = 1; off < 32; off <<= 1) {
        int y = __shfl_up_sync(0xffffffffu, x, off);
        if (lane >= off) x += y;
    }
    __syncthreads();
    if (lane == 31) wsum[wid] = x;
    __syncthreads();
    int excl_w = 0;
    for (int w = 0; w < 8; w++) if (w < wid) excl_w += wsum[w];
    if (i < n) {
        int rp = off0 + excl_w + x - v;
        g_row_ptr[i] = rp;
        g_cursor[i] = rp;
        g_dinv[i] = rsqrtf((float)v);
    }
    if (b == 0 && t == 0) g_row_ptr[n] = total;
}

// ---------------- CSR fill (edges + self-loops; per-CTA detect) ----------------
__global__ void fill_csr_kernel(const void* ei, int E, int n) {
    __shared__ int ismem[1];
    int is64 = detect_is64(ei, ismem);
    int i = blockIdx.x * blockDim.x + threadIdx.x;
    int total = E + n;
    if (i >= total) return;
    int s, d;
    if (i < E) {
        if (is64) {
            s = (int)((const long long*)ei)[i];
            d = (int)((const long long*)ei)[E + i];
        } else {
            s = ((const int*)ei)[i];
            d = ((const int*)ei)[E + i];
        }
    } else { s = d = i - E; }
    int pos = atomicAdd(&g_cursor[d], 1);
    g_csr[pos] = s;
    g_pdst[pos] = d;
}

// ---------------- GEMM1 (tiled, FFMA2): xw = x @ W_gcn, fp32 out ----------------
__global__ void gemm1_kernel(const float* __restrict__ x, const float* __restrict__ W, int n) {
    __shared__ float Ws[INDIM * HID];
    __shared__ float xs[128 * 32];
    int tid = threadIdx.x, q = tid & 15, rg = tid >> 4;
    for (int i = tid; i < INDIM * HID; i += 256) Ws[i] = W[i];
    int rowbase = blockIdx.x * 128;
    u64 accXY[8], accZW[8];
#pragma unroll
    for (int j = 0; j < 8; j++) { accXY[j] = 0ull; accZW[j] = 0ull; }
    const float4* x4 = (const float4*)x;
    float4* xs4 = (float4*)xs;
    const float4* Ws4 = (const float4*)Ws;
    for (int ch = 0; ch < 4; ch++) {
        __syncthreads();
        for (int l = tid; l < 1024; l += 256) {
            int r = l >> 3, c4 = l & 7;
            int row = rowbase + r;
            float4 v = make_float4(0.f, 0.f, 0.f, 0.f);
            if (row < n) v = x4[row * 32 + ch * 8 + c4];
            xs4[r * 8 + c4] = v;
        }
        __syncthreads();
#pragma unroll 4
        for (int kk = 0; kk < 32; kk++) {
            float4 w = Ws4[(ch * 32 + kk) * 16 + q];
            u64 wxy = pack2(w.x, w.y), wzw = pack2(w.z, w.w);
#pragma unroll
            for (int j = 0; j < 8; j++) {
                float xv = xs[(rg * 8 + j) * 32 + kk];
                u64 xv2 = pack2(xv, xv);
                ffma2(accXY[j], xv2, wxy);
                ffma2(accZW[j], xv2, wzw);
            }
        }
    }
    float4* xw4 = (float4*)g_xw;
#pragma unroll
    for (int j = 0; j < 8; j++) {
        int row = rowbase + rg * 8 + j;
        if (row < n) {
            float2 lo = unpack2(accXY[j]), hi = unpack2(accZW[j]);
            xw4[row * 16 + q] = make_float4(lo.x, lo.y, hi.x, hi.y);
        }
    }
}

// ---------------- GCN aggregate (fp32 gather, x2 unroll) + attention dots + deg reset ----------------
__global__ void gcn_agg_kernel(const float* __restrict__ b_gcn, int n) {
    int node = (blockIdx.x * blockDim.x + threadIdx.x) >> 5;
    int lane = threadIdx.x & 31;
    if (node >= n) return;
    int start = g_row_ptr[node], end = g_row_ptr[node + 1];
    float dn = g_dinv[node];
    const float2* xw2 = (const float2*)g_xw;
    float2 acc = make_float2(0.f, 0.f);
    int e = start;
    for (; e + 2 <= end; e += 2) {
        int s0 = g_csr[e], s1 = g_csr[e + 1];
        float w0 = g_dinv[s0] * dn, w1 = g_dinv[s1] * dn;
        float2 v0 = xw2[s0 * 32 + lane];
        float2 v1 = xw2[s1 * 32 + lane];
        acc.x += w0 * v0.x + w1 * v1.x;
        acc.y += w0 * v0.y + w1 * v1.y;
    }
    if (e < end) {
        int s = g_csr[e];
        float w = g_dinv[s] * dn;
        float2 v = xw2[s * 32 + lane];
        acc.x += w * v.x; acc.y += w * v.y;
    }
    float2 b = ((const float2*)b_gcn)[lane];
    float2 o;
    o.x = fmaxf(acc.x + b.x, 0.f);
    o.y = fmaxf(acc.y + b.y, 0.f);
    ((float2*)g_h1)[node * 32 + lane] = o;
    g_h1h[node * 32 + lane] = __floats2half2_rn(o.x, o.y);
    if (lane == 0) g_deg[node] = 0;     // reset for next replay

    const float2* ws2 = (const float2*)g_ws;
    const float2* wd2 = (const float2*)g_wd;
    float p[8];
#pragma unroll
    for (int h = 0; h < 4; h++) {
        float2 ws = ws2[h * 32 + lane];
        float2 wd = wd2[h * 32 + lane];
        p[h]     = o.x * ws.x + o.y * ws.y;
        p[4 + h] = o.x * wd.x + o.y * wd.y;
    }
#pragma unroll
    for (int off = 16; off; off >>= 1) {
#pragma unroll
        for (int j = 0; j < 8; j++) p[j] += __shfl_xor_sync(0xffffffffu, p[j], off);
    }
    if (lane == 0) {
        ((float4*)g_as)[node] = make_float4(p[0], p[1], p[2], p[3]);
        ((float4*)g_ad)[node] = make_float4(p[4], p[5], p[6], p[7]);
    }
}

// ---------------- GAT exp (edge-parallel, no max-sub; fp32 safe) ----------------
__global__ void gat_exp_kernel(int total) {
    int p = blockIdx.x * blockDim.x + threadIdx.x;
    if (p >= total) return;
    int s = g_csr[p];
    int d = g_pdst[p];
    float4 a  = ((const float4*)g_as)[s];
    float4 ad = ((const float4*)g_ad)[d];
    float4 o;
    o.x = __expf(lrelu(a.x + ad.x));
    o.y = __expf(lrelu(a.y + ad.y));
    o.z = __expf(lrelu(a.z + ad.z));
    o.w = __expf(lrelu(a.w + ad.w));
    g_exf[p] = o;
}

// ---------------- GAT aggregate (x2 unroll): fp32 ex, fp16 h1 gather -> u fp16 ----------------
__global__ void gat_agg_kernel(int n) {
    int node = (blockIdx.x * blockDim.x + threadIdx.x) >> 5;
    int lane = threadIdx.x & 31;
    if (node >= n) return;
    int start = g_row_ptr[node], end = g_row_ptr[node + 1];
    float acc[8];
#pragma unroll
    for (int i = 0; i < 8; i++) acc[i] = 0.f;
    float d0 = 0.f, d1 = 0.f, d2 = 0.f, d3 = 0.f;
    int e = start;
    for (; e + 2 <= end; e += 2) {
        int s0 = g_csr[e], s1 = g_csr[e + 1];
        float4 x0 = g_exf[e], x1 = g_exf[e + 1];
        float2 h0 = __half22float2(g_h1h[s0 * 32 + lane]);
        float2 h1v = __half22float2(g_h1h[s1 * 32 + lane]);
        d0 += x0.x + x1.x; d1 += x0.y + x1.y; d2 += x0.z + x1.z; d3 += x0.w + x1.w;
        acc[0] += x0.x * h0.x + x1.x * h1v.x;  acc[1] += x0.x * h0.y + x1.x * h1v.y;
        acc[2] += x0.y * h0.x + x1.y * h1v.x;  acc[3] += x0.y * h0.y + x1.y * h1v.y;
        acc[4] += x0.z * h0.x + x1.z * h1v.x;  acc[5] += x0.z * h0.y + x1.z * h1v.y;
        acc[6] += x0.w * h0.x + x1.w * h1v.x;  acc[7] += x0.w * h0.y + x1.w * h1v.y;
    }
    if (e < end) {
        int s = g_csr[e];
        float4 ex = g_exf[e];
        float2 hv = __half22float2(g_h1h[s * 32 + lane]);
        d0 += ex.x; d1 += ex.y; d2 += ex.z; d3 += ex.w;
        acc[0] += ex.x * hv.x; acc[1] += ex.x * hv.y;
        acc[2] += ex.y * hv.x; acc[3] += ex.y * hv.y;
        acc[4] += ex.z * hv.x; acc[5] += ex.z * hv.y;
        acc[6] += ex.w * hv.x; acc[7] += ex.w * hv.y;
    }
    float r0 = 1.f / d0, r1 = 1.f / d1, r2 = 1.f / d2, r3 = 1.f / d3;
    __half2* uh2 = (__half2*)g_uh;
    uh2[node * 128 +       lane] = __floats2half2_rn(acc[0] * r0, acc[1] * r0);
    uh2[node * 128 +  32 + lane] = __floats2half2_rn(acc[2] * r1, acc[3] * r1);
    uh2[node * 128 +  64 + lane] = __floats2half2_rn(acc[4] * r2, acc[5] * r2);
    uh2[node * 128 +  96 + lane] = __floats2half2_rn(acc[6] * r3, acc[7] * r3);
}

// ---------------- GEMM2b (WMMA fp16) + fused residual LayerNorm -> out ----------------
// h2 = relu(0.25 * u @ Wstack + b_gat); out = LN(h1 + h2 + hp)
__global__ void gemm2b_ln_kernel(const float* __restrict__ b_gat,
                                 const float* __restrict__ gamma, const float* __restrict__ beta,
                                 float* __restrict__ out, int n) {
    extern __shared__ char dynsmem[];
    __half* Wst = (__half*)dynsmem;                 // 256*64 half = 32 KB
    float*  ot  = (float*)(dynsmem + 32768);        // 128*64 float = 32 KB
    int tid = threadIdx.x, warp = tid >> 5;
    int rowbase = blockIdx.x * 128;

    // load Wstack fp16 into smem
    const __half2* wsrc = (const __half2*)g_wsth;
    __half2* wdst = (__half2*)Wst;
    for (int i = tid; i < 256 * HID / 2; i += 256) wdst[i] = wsrc[i];
    __syncthreads();

    // each warp computes a 16x64 output slab: rows rowbase+warp*16 ..
    wmma::fragment<wmma::accumulator, 16, 16, 16, float> accf[4];
#pragma unroll
    for (int j = 0; j < 4; j++) wmma::fill_fragment(accf[j], 0.f);
    wmma::fragment<wmma::matrix_a, 16, 16, 16, __half, wmma::row_major> af;
    wmma::fragment<wmma::matrix_b, 16, 16, 16, __half, wmma::row_major> bf;
    const __half* abase = g_uh + (size_t)(rowbase + warp * 16) * 256;
    for (int k = 0; k < 256; k += 16) {
        wmma::load_matrix_sync(af, abase + k, 256);
#pragma unroll
        for (int j = 0; j < 4; j++) {
            wmma::load_matrix_sync(bf, Wst + k * 64 + j * 16, 64);
            wmma::mma_sync(accf[j], af, bf, accf[j]);
        }
    }
#pragma unroll
    for (int j = 0; j < 4; j++)
        wmma::store_matrix_sync(ot + warp * 16 * 64 + j * 16, accf[j], 64, wmma::mem_row_major);
    __syncthreads();

    // LN epilogue (identical structure to round-8)
    int q = tid & 15, rg = tid >> 4;
    float4 b   = ((const float4*)b_gat)[q];
    float4 g4  = ((const float4*)gamma)[q];
    float4 bt4 = ((const float4*)beta)[q];
    const float4* h1_4 = (const float4*)g_h1;
    const float4* hp4  = (const float4*)g_hp;
    const float4* ot4  = (const float4*)ot;
    float4* out4 = (float4*)out;
#pragma unroll
    for (int j = 0; j < 8; j++) {
        int r = rg * 8 + j;
        int row = rowbase + r;
        float4 a = ot4[r * 16 + q];
        float4 h2v;
        h2v.x = fmaxf(0.25f * a.x + b.x, 0.f);
        h2v.y = fmaxf(0.25f * a.y + b.y, 0.f);
        h2v.z = fmaxf(0.25f * a.z + b.z, 0.f);
        h2v.w = fmaxf(0.25f * a.w + b.w, 0.f);
        float4 h1v = (row < n) ? h1_4[row * 16 + q] : make_float4(0.f, 0.f, 0.f, 0.f);
        float4 hpv = (row < n) ? hp4[row * 16 + q]  : make_float4(0.f, 0.f, 0.f, 0.f);
        float4 h;
        h.x = h1v.x + h2v.x + hpv.x;
        h.y = h1v.y + h2v.y + hpv.y;
        h.z = h1v.z + h2v.z + hpv.z;
        h.w = h1v.w + h2v.w + hpv.w;
        float s  = h.x + h.y + h.z + h.w;
        float sq = h.x * h.x + h.y * h.y + h.z * h.z + h.w * h.w;
#pragma unroll
        for (int off = 8; off; off >>= 1) {
            s  += __shfl_xor_sync(0xffffffffu, s, off);
            sq += __shfl_xor_sync(0xffffffffu, sq, off);
        }
        float mu = s * (1.f / 64.f);
        float var = sq * (1.f / 64.f) - mu * mu;
        float rstd = rsqrtf(var + 1e-5f);
        if (row < n) {
            float4 o;
            o.x = (h.x - mu) * rstd * g4.x + bt4.x;
            o.y = (h.y - mu) * rstd * g4.y + bt4.y;
            o.z = (h.z - mu) * rstd * g4.z + bt4.z;
            o.w = (h.w - mu) * rstd * g4.w + bt4.w;
            out4[row * 16 + q] = o;
        }
    }
}

// ---------------- patch GEMM (side stream, concurrent with GAT) ----------------
__global__ void patch_kernel(const float* __restrict__ Wp, const float* __restrict__ b_patch, int n) {
    __shared__ float Ws[HID * HID];
    __shared__ float hs[128 * HID];
    int tid = threadIdx.x, q = tid & 15, rg = tid >> 4;
    for (int i = tid; i < HID * HID; i += 256) Ws[i] = Wp[i];
    int rowbase = blockIdx.x * 128;
    const float4* h1_4 = (const float4*)g_h1;
    float4* hs4 = (float4*)hs;
    for (int l = tid; l < 2048; l += 256) {
        int r = l >> 4, c4 = l & 15;
        int row = rowbase + r;
        hs4[l] = (row < n) ? h1_4[row * 16 + c4] : make_float4(0.f, 0.f, 0.f, 0.f);
    }
    __syncthreads();
    u64 accXY[8], accZW[8];
#pragma unroll
    for (int j = 0; j < 8; j++) { accXY[j] = 0ull; accZW[j] = 0ull; }
    const float4* Ws4 = (const float4*)Ws;
#pragma unroll 4
    for (int k = 0; k < HID; k++) {
        float4 w = Ws4[k * 16 + q];
        u64 wxy = pack2(w.x, w.y), wzw = pack2(w.z, w.w);
#pragma unroll
        for (int j = 0; j < 8; j++) {
            float hv = hs[(rg * 8 + j) * HID + k];
            u64 hv2 = pack2(hv, hv);
            ffma2(accXY[j], hv2, wxy);
            ffma2(accZW[j], hv2, wzw);
        }
    }
    float4 bp = ((const float4*)b_patch)[q];
    float4* hp4 = (float4*)g_hp;
#pragma unroll
    for (int j = 0; j < 8; j++) {
        int row = rowbase + rg * 8 + j;
        if (row < n) {
            float2 lo = unpack2(accXY[j]), hi = unpack2(accZW[j]);
            hp4[row * 16 + q] = make_float4(lo.x + bp.x, lo.y + bp.y, hi.x + bp.z, hi.y + bp.w);
        }
    }
}

// ---------------- launch (forked capture) ----------------
extern "C" void kernel_launch(void* const* d_in, const int* in_sizes, int n_in,
                              void* d_out, int out_size) {
    const float* x        = (const float*)d_in[0];
    const void*  ei       = d_in[1];
    const float* W_gcn    = (const float*)d_in[2];
    const float* b_gcn    = (const float*)d_in[3];
    const float* W_gat    = (const float*)d_in[4];
    const float* att_src  = (const float*)d_in[5];
    const float* att_dst  = (const float*)d_in[6];
    const float* b_gat    = (const float*)d_in[7];
    const float* W_patch  = (const float*)d_in[8];
    const float* b_patch  = (const float*)d_in[9];
    const float* gamma    = (const float*)d_in[10];
    const float* beta     = (const float*)d_in[11];
    float* out = (float*)d_out;

    int n = in_sizes[0] / INDIM;          // 50000
    int E = in_sizes[1] / 2;              // 400000

    static cudaStream_t s2 = nullptr;
    static cudaEvent_t evFork = nullptr, evG = nullptr, evH1 = nullptr, evJoin = nullptr;
    if (s2 == nullptr) {
        cudaStreamCreateWithFlags(&s2, cudaStreamNonBlocking);
        cudaEventCreateWithFlags(&evFork, cudaEventDisableTiming);
        cudaEventCreateWithFlags(&evG,    cudaEventDisableTiming);
        cudaEventCreateWithFlags(&evH1,   cudaEventDisableTiming);
        cudaEventCreateWithFlags(&evJoin, cudaEventDisableTiming);
        cudaFuncSetAttribute(gemm2b_ln_kernel,
                             cudaFuncAttributeMaxDynamicSharedMemorySize, 65536);
    }

    const int T = 256;
    int gN   = (n + T - 1) / T;
    int gE4  = (E / 4 + T) / T;
    int gEN  = (E + n + T - 1) / T;
    int g128 = (n + 127) / 128;
    int gWpN = (n * 32 + T - 1) / T;

    // fork: gemm1 + weight prep run concurrently with graph build
    cudaEventRecord(evFork, 0);
    cudaStreamWaitEvent(s2, evFork, 0);
    prep2_kernel<<<1, 256, 0, s2>>>(W_gat, att_src, att_dst);
    gemm1_kernel<<<g128, T, 0, s2>>>(x, W_gcn, n);
    cudaEventRecord(evG, s2);

    // main chain: graph build
    hist_kernel<<<gE4, T>>>(ei, E);
    scan_kernel<<<gN, 256>>>(n, E + n);
    fill_csr_kernel<<<gEN, T>>>(ei, E, n);

    cudaStreamWaitEvent(0, evG, 0);
    gcn_agg_kernel<<<gWpN, T>>>(b_gcn, n);
    cudaEventRecord(evH1, 0);

    // side stream: patch GEMM concurrent with GAT
    cudaStreamWaitEvent(s2, evH1, 0);
    patch_kernel<<<g128, T, 0, s2>>>(W_patch, b_patch, n);
    cudaEventRecord(evJoin, s2);

    gat_exp_kernel<<<gEN, T>>>(E + n);
    gat_agg_kernel<<<gWpN, T>>>(n);

    cudaStreamWaitEvent(0, evJoin, 0);
    gemm2b_ln_kernel<<<g128, T, 65536>>>(b_gat, gamma, beta, out, n);
}